// round 17
// baseline (speedup 1.0000x reference)
#include <cuda_runtime.h>
#include <math.h>

#define NCLS 19
#define DD   128
#define HWP  65536          // H*W
#define BB   8
#define NPIX (BB*HWP)       // 524288

#define P1_BLOCKS  592              // 4 x 148 SMs, single wave
#define P1_THREADS 288              // 8 MMA warps (dims) + 1 label warp
#define P1_CHUNK   128              // pixels per chunk (8 ksteps)
#define P1_NCHUNK  (NPIX/P1_CHUNK)  // 4096

#define P2_BLOCKS  592              // 4 x 148 SMs, single wave
#define P2_THREADS 256              // 8 MMA warps; warp w owns px [16w,16w+16)
#define P2_CHUNK   128
#define P2_NCHUNK  (NPIX/P2_CHUNK)  // 4096
#define MB_STRIDE  132              // bf16 means row stride (conflict-light)
#define ST_STRIDE  26               // staging row stride (floats)

// ---- static scratch (no allocations allowed; zero-init at load) ----
__device__ float          g_sums[NCLS*DD];
__device__ int            g_cnt[NCLS];
__device__ float          g_var[NCLS];
__device__ unsigned int   g_done2;
__device__ unsigned char  g_labs[NPIX];

// ---------------------------------------------------------------- pass 1
// Segment-sum as GEMM: D[d][c] = sum_p feats[d][p] * onehot(lab[p]==c).
// Warps 0..7: mma.sync.m16n8k16, A = feats [16 dims x 16 px] bf16 loaded
// straight from global in fragment layout (__ldcs), B = onehot built in
// registers from raw int32 labels, C = fp32 [16 d x 24 cls]; single
// atomic writeout. Warp 8: label histogram + pack (replaces prep kernel).
__global__ void __launch_bounds__(P1_THREADS, 4) k_pass1(const float* __restrict__ feats,
                                                         const int* __restrict__ labels) {
    __shared__ int hist[NCLS];
    int w    = threadIdx.x >> 5;
    int lane = threadIdx.x & 31;

    if (w == 8) {
        // ---------------- label warp: histogram + pack ----------------
        if (lane < NCLS) hist[lane] = 0;
        __syncwarp();
        for (int ch = blockIdx.x; ch < P1_NCHUNK; ch += P1_BLOCKS) {
            int pxg = ch * P1_CHUNK;
            int4 lv = ((const int4*)(labels + pxg))[lane];   // 4 labels/lane
            uchar4 u;
            u.x = (lv.x >= 0 && lv.x < NCLS) ? (unsigned char)lv.x : (unsigned char)255;
            u.y = (lv.y >= 0 && lv.y < NCLS) ? (unsigned char)lv.y : (unsigned char)255;
            u.z = (lv.z >= 0 && lv.z < NCLS) ? (unsigned char)lv.z : (unsigned char)255;
            u.w = (lv.w >= 0 && lv.w < NCLS) ? (unsigned char)lv.w : (unsigned char)255;
            ((uchar4*)(g_labs + pxg))[lane] = u;
            if (u.x < NCLS) atomicAdd(&hist[u.x], 1);
            if (u.y < NCLS) atomicAdd(&hist[u.y], 1);
            if (u.z < NCLS) atomicAdd(&hist[u.z], 1);
            if (u.w < NCLS) atomicAdd(&hist[u.w], 1);
        }
        __syncwarp();
        if (lane < NCLS) atomicAdd(&g_cnt[lane], hist[lane]);
        return;
    }

    // ---------------- MMA warps: segment-sum GEMM ----------------
    int gid  = lane >> 2;            // 0..7
    int ktid = lane & 3;             // 0..3
    int d_lo = w*16 + gid;

    float c0[4] = {0.f,0.f,0.f,0.f};
    float c1[4] = {0.f,0.f,0.f,0.f};
    float c2[4] = {0.f,0.f,0.f,0.f};

    for (int ch = blockIdx.x; ch < P1_NCHUNK; ch += P1_BLOCKS) {
        int pxg = ch * P1_CHUNK;         // plane-aligned: 128 | 65536
        int b   = pxg >> 16;
        int po  = pxg & 65535;
        const float* rowA = feats + ((size_t)b*DD + d_lo    ) * HWP + po;
        const float* rowB = feats + ((size_t)b*DD + d_lo + 8) * HWP + po;
        const int*   labp = labels + pxg;

        #pragma unroll 2
        for (int ks = 0; ks < P1_CHUNK/16; ks++) {
            int p0 = ks*16 + 2*ktid;     // thread's k-anchor within the 16-px tile
            float2 fa0 = __ldcs((const float2*)(rowA + p0));        // A[gid][k0,k0+1]
            float2 fa1 = __ldcs((const float2*)(rowB + p0));        // A[gid+8][k0,k0+1]
            float2 fa2 = __ldcs((const float2*)(rowA + p0 + 8));    // A[gid][k0+8,k0+9]
            float2 fa3 = __ldcs((const float2*)(rowB + p0 + 8));    // A[gid+8][k0+8,k0+9]
            unsigned a0, a1, a2, a3;
            asm("cvt.rn.bf16x2.f32 %0, %1, %2;" : "=r"(a0) : "f"(fa0.y), "f"(fa0.x));
            asm("cvt.rn.bf16x2.f32 %0, %1, %2;" : "=r"(a1) : "f"(fa1.y), "f"(fa1.x));
            asm("cvt.rn.bf16x2.f32 %0, %1, %2;" : "=r"(a2) : "f"(fa2.y), "f"(fa2.x));
            asm("cvt.rn.bf16x2.f32 %0, %1, %2;" : "=r"(a3) : "f"(fa3.y), "f"(fa3.x));

            int2 L01 = *(const int2*)(labp + p0);       // L1/L2 hit (8 warps share)
            int2 L89 = *(const int2*)(labp + p0 + 8);
            int l0 = L01.x, l1 = L01.y;
            int l8 = L89.x, l9 = L89.y;

            {   int cls = gid;                       // tile 0: classes 0..7
                unsigned b0 = (l0==cls ? 0x3F80u : 0u) | (l1==cls ? 0x3F800000u : 0u);
                unsigned b1 = (l8==cls ? 0x3F80u : 0u) | (l9==cls ? 0x3F800000u : 0u);
                asm("mma.sync.aligned.m16n8k16.row.col.f32.bf16.bf16.f32 "
                    "{%0,%1,%2,%3}, {%4,%5,%6,%7}, {%8,%9}, {%0,%1,%2,%3};"
                    : "+f"(c0[0]), "+f"(c0[1]), "+f"(c0[2]), "+f"(c0[3])
                    : "r"(a0), "r"(a1), "r"(a2), "r"(a3), "r"(b0), "r"(b1));
            }
            {   int cls = gid + 8;                   // tile 1: classes 8..15
                unsigned b0 = (l0==cls ? 0x3F80u : 0u) | (l1==cls ? 0x3F800000u : 0u);
                unsigned b1 = (l8==cls ? 0x3F80u : 0u) | (l9==cls ? 0x3F800000u : 0u);
                asm("mma.sync.aligned.m16n8k16.row.col.f32.bf16.bf16.f32 "
                    "{%0,%1,%2,%3}, {%4,%5,%6,%7}, {%8,%9}, {%0,%1,%2,%3};"
                    : "+f"(c1[0]), "+f"(c1[1]), "+f"(c1[2]), "+f"(c1[3])
                    : "r"(a0), "r"(a1), "r"(a2), "r"(a3), "r"(b0), "r"(b1));
            }
            {   int cls = gid + 16;                  // tile 2: classes 16..23
                unsigned b0 = (l0==cls ? 0x3F80u : 0u) | (l1==cls ? 0x3F800000u : 0u);
                unsigned b1 = (l8==cls ? 0x3F80u : 0u) | (l9==cls ? 0x3F800000u : 0u);
                asm("mma.sync.aligned.m16n8k16.row.col.f32.bf16.bf16.f32 "
                    "{%0,%1,%2,%3}, {%4,%5,%6,%7}, {%8,%9}, {%0,%1,%2,%3};"
                    : "+f"(c2[0]), "+f"(c2[1]), "+f"(c2[2]), "+f"(c2[3])
                    : "r"(a0), "r"(a1), "r"(a2), "r"(a3), "r"(b0), "r"(b1));
            }
        }
    }

    // writeout: C[m][n] -> d = w*16 + m (m = gid, gid+8), cls = 8t + n
    int dA = w*16 + gid, dB = dA + 8;
    {   int n0 = 2*ktid, n1 = n0 + 1;             // tile 0: cls 0..7
        atomicAdd(&g_sums[n0*DD + dA], c0[0]);
        atomicAdd(&g_sums[n1*DD + dA], c0[1]);
        atomicAdd(&g_sums[n0*DD + dB], c0[2]);
        atomicAdd(&g_sums[n1*DD + dB], c0[3]);
    }
    {   int n0 = 8 + 2*ktid, n1 = n0 + 1;         // tile 1: cls 8..15
        atomicAdd(&g_sums[n0*DD + dA], c1[0]);
        atomicAdd(&g_sums[n1*DD + dA], c1[1]);
        atomicAdd(&g_sums[n0*DD + dB], c1[2]);
        atomicAdd(&g_sums[n1*DD + dB], c1[3]);
    }
    {   int n0 = 16 + 2*ktid, n1 = n0 + 1;        // tile 2: cls 16..23 (keep <19)
        if (n0 < NCLS) { atomicAdd(&g_sums[n0*DD + dA], c2[0]);
                         atomicAdd(&g_sums[n0*DD + dB], c2[2]); }
        if (n1 < NCLS) { atomicAdd(&g_sums[n1*DD + dA], c2[1]);
                         atomicAdd(&g_sums[n1*DD + dB], c2[3]); }
    }
}

// ---------------------------------------------------------------- pass 2
// Gram-expansion GEMM (pass1-shaped): P[px][cls] = f_px . m_cls via
// mma.m16n8k16 with A = feats [16px x 16d] fragments (scattered 4-plane x
// 32B warp requests -- pass1's 68%-DRAM load shape), B = bf16 means from
// smem, C = fp32. ||f||^2 accumulated in fp32 from the same loads.
// dist^2 = ||f||^2 - 2*P[px][lab] + ||m_lab||^2, then hinge + class atomic.
// Grid 592 @4/SM, grid-stride over 4096 chunks of 128 px (8 warps x 16).
__global__ void __launch_bounds__(P2_THREADS, 4) k_pass2(const float* __restrict__ feats,
                                                         float* __restrict__ out) {
    __shared__ unsigned short mb[24*MB_STRIDE];   // bf16 means, padded rows
    __shared__ float msq[NCLS];                   // ||m_c||^2 (fp32)
    __shared__ float vs[NCLS];
    __shared__ float stage[8*16*ST_STRIDE];       // per-warp P staging (3328 f)
    int t    = threadIdx.x;
    int w    = t >> 5;
    int lane = t & 31;
    int gid  = lane >> 2;            // 0..7
    int ktid = lane & 3;             // 0..3

    // build bf16 means (classes 19..23 = zero pad)
    for (int i = t; i < 24*DD; i += P2_THREADS) {
        int c = i >> 7, d = i & 127;
        float m = 0.f;
        if (c < NCLS) m = g_sums[c*DD + d] / fmaxf((float)g_cnt[c], 1.f);
        unsigned short mh;
        asm("cvt.rn.bf16.f32 %0, %1;" : "=h"(mh) : "f"(m));
        mb[c*MB_STRIDE + d] = mh;
    }
    if (t < NCLS) {
        float s = 0.f;
        float inv = 1.f / fmaxf((float)g_cnt[t], 1.f);
        #pragma unroll 16
        for (int d = 0; d < DD; d++) { float m = g_sums[t*DD + d] * inv; s = fmaf(m, m, s); }
        msq[t] = s;
        vs[t]  = 0.f;
    }
    __syncthreads();

    float* st = stage + w*16*ST_STRIDE;

    for (int ch = blockIdx.x; ch < P2_NCHUNK; ch += P2_BLOCKS) {
        int pxg = ch * P2_CHUNK;         // plane-aligned: 128 | 65536
        int b   = pxg >> 16;
        int po  = pxg & 65535;
        const float* colA = feats + (size_t)b*DD*HWP + po + w*16 + gid;      // px A
        const float* colB = colA + 8;                                        // px B

        float c0[4] = {0.f,0.f,0.f,0.f};
        float c1[4] = {0.f,0.f,0.f,0.f};
        float c2[4] = {0.f,0.f,0.f,0.f};
        float sA = 0.f, sB = 0.f;

        #pragma unroll
        for (int ks = 0; ks < 8; ks++) {
            int d0 = ks*16 + 2*ktid;     // thread's k-anchor (d dimension)
            float fA0 = __ldcs(colA + (size_t)(d0    )*HWP);
            float fA1 = __ldcs(colA + (size_t)(d0 + 1)*HWP);
            float fB0 = __ldcs(colB + (size_t)(d0    )*HWP);
            float fB1 = __ldcs(colB + (size_t)(d0 + 1)*HWP);
            float fA8 = __ldcs(colA + (size_t)(d0 + 8)*HWP);
            float fA9 = __ldcs(colA + (size_t)(d0 + 9)*HWP);
            float fB8 = __ldcs(colB + (size_t)(d0 + 8)*HWP);
            float fB9 = __ldcs(colB + (size_t)(d0 + 9)*HWP);

            sA = fmaf(fA0, fA0, sA); sA = fmaf(fA1, fA1, sA);
            sA = fmaf(fA8, fA8, sA); sA = fmaf(fA9, fA9, sA);
            sB = fmaf(fB0, fB0, sB); sB = fmaf(fB1, fB1, sB);
            sB = fmaf(fB8, fB8, sB); sB = fmaf(fB9, fB9, sB);

            unsigned a0, a1, a2, a3;
            asm("cvt.rn.bf16x2.f32 %0, %1, %2;" : "=r"(a0) : "f"(fA1), "f"(fA0));
            asm("cvt.rn.bf16x2.f32 %0, %1, %2;" : "=r"(a1) : "f"(fB1), "f"(fB0));
            asm("cvt.rn.bf16x2.f32 %0, %1, %2;" : "=r"(a2) : "f"(fA9), "f"(fA8));
            asm("cvt.rn.bf16x2.f32 %0, %1, %2;" : "=r"(a3) : "f"(fB9), "f"(fB8));

            {   int cls = gid;                       // tile 0: classes 0..7
                unsigned b0 = *(const unsigned*)(mb + cls*MB_STRIDE + d0);
                unsigned b1 = *(const unsigned*)(mb + cls*MB_STRIDE + d0 + 8);
                asm("mma.sync.aligned.m16n8k16.row.col.f32.bf16.bf16.f32 "
                    "{%0,%1,%2,%3}, {%4,%5,%6,%7}, {%8,%9}, {%0,%1,%2,%3};"
                    : "+f"(c0[0]), "+f"(c0[1]), "+f"(c0[2]), "+f"(c0[3])
                    : "r"(a0), "r"(a1), "r"(a2), "r"(a3), "r"(b0), "r"(b1));
            }
            {   int cls = gid + 8;                   // tile 1: classes 8..15
                unsigned b0 = *(const unsigned*)(mb + cls*MB_STRIDE + d0);
                unsigned b1 = *(const unsigned*)(mb + cls*MB_STRIDE + d0 + 8);
                asm("mma.sync.aligned.m16n8k16.row.col.f32.bf16.bf16.f32 "
                    "{%0,%1,%2,%3}, {%4,%5,%6,%7}, {%8,%9}, {%0,%1,%2,%3};"
                    : "+f"(c1[0]), "+f"(c1[1]), "+f"(c1[2]), "+f"(c1[3])
                    : "r"(a0), "r"(a1), "r"(a2), "r"(a3), "r"(b0), "r"(b1));
            }
            {   int cls = gid + 16;                  // tile 2: classes 16..23
                unsigned b0 = *(const unsigned*)(mb + cls*MB_STRIDE + d0);
                unsigned b1 = *(const unsigned*)(mb + cls*MB_STRIDE + d0 + 8);
                asm("mma.sync.aligned.m16n8k16.row.col.f32.bf16.bf16.f32 "
                    "{%0,%1,%2,%3}, {%4,%5,%6,%7}, {%8,%9}, {%0,%1,%2,%3};"
                    : "+f"(c2[0]), "+f"(c2[1]), "+f"(c2[2]), "+f"(c2[3])
                    : "r"(a0), "r"(a1), "r"(a2), "r"(a3), "r"(b0), "r"(b1));
            }
        }

        // ||f||^2: reduce partials over ktid (lane = gid*4 + ktid)
        sA += __shfl_down_sync(0xffffffffu, sA, 1);
        sA += __shfl_down_sync(0xffffffffu, sA, 2);
        sB += __shfl_down_sync(0xffffffffu, sB, 1);
        sB += __shfl_down_sync(0xffffffffu, sB, 2);

        // stage P: C[m][n] -> px = (gid, gid+8), cls = tile*8 + (2ktid, 2ktid+1)
        st[ gid    *ST_STRIDE + 2*ktid     ] = c0[0];
        st[ gid    *ST_STRIDE + 2*ktid + 1 ] = c0[1];
        st[(gid+8) *ST_STRIDE + 2*ktid     ] = c0[2];
        st[(gid+8) *ST_STRIDE + 2*ktid + 1 ] = c0[3];
        st[ gid    *ST_STRIDE + 8 + 2*ktid     ] = c1[0];
        st[ gid    *ST_STRIDE + 8 + 2*ktid + 1 ] = c1[1];
        st[(gid+8) *ST_STRIDE + 8 + 2*ktid     ] = c1[2];
        st[(gid+8) *ST_STRIDE + 8 + 2*ktid + 1 ] = c1[3];
        st[ gid    *ST_STRIDE + 16 + 2*ktid     ] = c2[0];
        st[ gid    *ST_STRIDE + 16 + 2*ktid + 1 ] = c2[1];
        st[(gid+8) *ST_STRIDE + 16 + 2*ktid     ] = c2[2];
        st[(gid+8) *ST_STRIDE + 16 + 2*ktid + 1 ] = c2[3];
        __syncwarp();

        if (ktid == 0) {
            int pA = pxg + w*16 + gid;
            int labA = g_labs[pA];
            if (labA < NCLS) {
                float P  = st[gid*ST_STRIDE + labA];
                float d2 = fmaxf(sA - 2.f*P + msq[labA], 0.f);
                float h  = fmaxf(sqrtf(d2) - 0.5f, 0.f);       // DELTA_V = 0.5
                atomicAdd(&vs[labA], h*h);
            }
            int labB = g_labs[pA + 8];
            if (labB < NCLS) {
                float P  = st[(gid+8)*ST_STRIDE + labB];
                float d2 = fmaxf(sB - 2.f*P + msq[labB], 0.f);
                float h  = fmaxf(sqrtf(d2) - 0.5f, 0.f);
                atomicAdd(&vs[labB], h*h);
            }
        }
        __syncwarp();                    // staging reusable next chunk
    }
    __syncthreads();
    if (t < NCLS) atomicAdd(&g_var[t], vs[t]);

    // ---- last-arriving block: final loss assembly + scratch reset ----
    __threadfence();
    __shared__ bool isLast;
    if (t == 0) isLast = (atomicAdd(&g_done2, 1u) == P2_BLOCKS - 1);
    __syncthreads();
    if (!isLast) return;

    float* msf = stage;                  // reuse staging as fp32 means [19*128]
    for (int i = t; i < NCLS*DD; i += P2_THREADS) {
        int c = i >> 7;
        msf[i] = g_sums[i] / fmaxf((float)g_cnt[c], 1.f);
    }
    __syncthreads();

    __shared__ float vld[NCLS];
    __shared__ float sreg[NCLS];
    __shared__ float spair[NCLS*NCLS];
    if (t < NCLS) {
        vld[t]  = (g_cnt[t] > 100) ? 1.f : 0.f;   // MAX_VIEWS = 100, strict >
        sreg[t] = (msq[t] > 0.f) ? sqrtf(msq[t]) : 0.f;
    }
    for (int idx = t; idx < NCLS*NCLS; idx += P2_THREADS) {
        int a = idx / NCLS, b2 = idx % NCLS;
        float s = 0.f;
        #pragma unroll 16
        for (int d = 0; d < DD; d++) {
            float diff = msf[a*DD + d] - msf[b2*DD + d];
            s = fmaf(diff, diff, s);
        }
        float pdn = (s > 0.f) ? sqrtf(s) : 0.f;
        float hd  = fmaxf(2.f*1.5f - pdn, 0.f);   // 2*DELTA_D
        spair[idx] = hd*hd;
    }
    // reset g_sums for next replay (all reads of g_sums are done)
    for (int i = t; i < NCLS*DD; i += P2_THREADS) g_sums[i] = 0.f;
    __syncthreads();
    if (t == 0) {
        int last = -1;
        for (int c = 0; c < NCLS; c++) if (vld[c] > 0.f) last = c;
        float tc = 0.f, lvar = 0.f, lreg = 0.f, ldist = 0.f;
        for (int c = 0; c < NCLS; c++) {
            if (vld[c] > 0.f) {
                tc   += 1.f;
                lvar += g_var[c] / fmaxf((float)g_cnt[c], 1.f);
                lreg += sreg[c];
            }
        }
        // faithful buggy double loop: a over all valid, b over valid except
        // the LAST valid class id; includes a == b pairs.
        for (int a = 0; a < NCLS; a++)
            for (int b2 = 0; b2 < NCLS; b2++)
                if (vld[a] > 0.f && vld[b2] > 0.f && b2 != last)
                    ldist += spair[a*NCLS + b2];
        out[0] = lvar/tc + ldist/(tc*(tc - 1.f)) + 0.001f*lreg/tc;  // ALPHA=BETA=1, GAMMA=1e-3
        // reset for next replay (g_cnt is re-accumulated by pass1)
        for (int c = 0; c < NCLS; c++) { g_var[c] = 0.f; g_cnt[c] = 0; }
        g_done2 = 0u;
    }
}

// ---------------------------------------------------------------- launch
extern "C" void kernel_launch(void* const* d_in, const int* in_sizes, int n_in,
                              void* d_out, int out_size) {
    const float* feats  = (const float*)d_in[0];
    const int*   labels = (const int*)d_in[1];
    float* out = (float*)d_out;

    k_pass1<<<P1_BLOCKS, P1_THREADS>>>(feats, labels);
    k_pass2<<<P2_BLOCKS, P2_THREADS>>>(feats, out);
}